// round 9
// baseline (speedup 1.0000x reference)
#include <cuda_runtime.h>
#include <cuda_bf16.h>

// Problem constants
#define GR      64                 // grid resolution per axis
#define NB      8                  // batch
#define NP      4096               // points per batch
#define CHUNK   64                 // points per sub-chunk (shared tile)
#define CPB     4                  // sub-chunks per block
#define NPART   (NP / (CHUNK*CPB)) // 16 partial tiles per batch
#define GG      (GR * GR)          // 4096 grid points

// Partial accumulators: [b][part][3][GG] -> 8*16*3*4096 floats = 6.3 MB
__device__ float g_partial[NB * NPART * 3 * GG];

// ---------- f32x2 packed helpers (sm_103a FFMA2 path, PTX-only) ----------
__device__ __forceinline__ unsigned long long splat2(float a) {
    unsigned long long r;
    asm("mov.b64 %0, {%1, %1};" : "=l"(r) : "f"(a));
    return r;
}
__device__ __forceinline__ void unpack2(unsigned long long v, float& lo, float& hi) {
    asm("mov.b64 {%0, %1}, %2;" : "=f"(lo), "=f"(hi) : "l"(v));
}
#define FMA2(acc, a, b) asm("fma.rn.f32x2 %0, %1, %2, %0;" : "+l"(acc) : "l"(a), "l"(b))

// Dynamic smem: 2 buffers x 4 planes (U,V,VY,VT) x 4096 floats = 128 KB
extern __shared__ float dynsmem[];
#define PLANE(q, k) (dynsmem + ((q) * 4 + (k)) * (CHUNK * 64))

// One Phase-A burst: thread owns point p = tid>>2 (scalars in regs) and
// g-column group gq = tid&3 (16 g each); burst i4 covers 4 consecutive g.
// Writes U/V/VY/VT rows of buffer q with STS.128.
__device__ __forceinline__ void phaseA_iter(int i4, int q, int p, int gq,
                                            float x0, float x1, float yv,
                                            float tv, float mk)
{
    const int g0 = gq * 16 + i4 * 4;
    float u[4], v[4];
    #pragma unroll
    for (int e = 0; e < 4; e++) {
        const float cg = -1.0f + (float)(g0 + e) * (2.0f / 63.0f);
        const float dx = x0 - cg;
        const float dy = x1 - cg;
        u[e] = mk * __expf(-50.0f * dx * dx);
        v[e] =      __expf(-50.0f * dy * dy);
    }
    const int off = p * 64 + g0;
    *reinterpret_cast<float4*>(PLANE(q, 0) + off) = make_float4(u[0], u[1], u[2], u[3]);
    *reinterpret_cast<float4*>(PLANE(q, 1) + off) = make_float4(v[0], v[1], v[2], v[3]);
    *reinterpret_cast<float4*>(PLANE(q, 2) + off) =
        make_float4(v[0] * yv, v[1] * yv, v[2] * yv, v[3] * yv);
    *reinterpret_cast<float4*>(PLANE(q, 3) + off) =
        make_float4(v[0] * tv, v[1] * tv, v[2] * tv, v[3] * tv);
}

// Kernel 1: per (batch, 256-point group) block. Rank-1 FMA2 accumulation with
// software-pipelined table construction (exp work hides under the fma shadow).
__global__ __launch_bounds__(256)
void rbf_partial_kernel(const float* __restrict__ x_c,
                        const float* __restrict__ y_c,
                        const float* __restrict__ t_c,
                        const int*   __restrict__ mask)
{
    const int part = blockIdx.x;        // 0..NPART-1
    const int b    = blockIdx.y;        // 0..NB-1
    const int tid  = threadIdx.x;       // 0..255

    // Phase B tile mapping: 4 gy (2 f32x2 pairs) x 4 gx per thread
    const int gyg = tid >> 4;           // 0..15
    const int gxg = tid & 15;           // 0..15
    // Phase A mapping: point p, g-column group gq
    const int p  = tid >> 2;            // 0..63
    const int gq = tid & 3;             // 0..3

    const int base = b * NP + part * (CHUNK * CPB);

    // accumulators: [gx 0..3][gy-pair 0..1]
    unsigned long long aD[4][2], aY[4][2], aT[4][2];
    #pragma unroll
    for (int i = 0; i < 4; i++)
        #pragma unroll
        for (int j = 0; j < 2; j++) { aD[i][j] = 0ull; aY[i][j] = 0ull; aT[i][j] = 0ull; }

    // ---- prologue: build tables for chunk 0 into buffer 0 ----
    {
        const int n0 = base + p;
        const float x0 = x_c[2 * n0 + 0];
        const float x1 = x_c[2 * n0 + 1];
        const float yv = y_c[n0];
        const float tv = t_c[n0];
        const float mk = (mask[n0] != 0) ? 0.0f : 1.0f;
        #pragma unroll
        for (int i4 = 0; i4 < 4; i4++)
            phaseA_iter(i4, 0, p, gq, x0, x1, yv, tv, mk);
    }
    __syncthreads();

    #pragma unroll 1
    for (int c = 0; c < CPB; c++) {
        const int q  = c & 1;           // buffer holding chunk c
        const int qn = q ^ 1;           // buffer for chunk c+1
        const bool pre = (c + 1 < CPB);

        // prefetch next chunk's point scalars into registers (LDG, hidden)
        float nx0 = 0.f, nx1 = 0.f, nyv = 0.f, ntv = 0.f, nmk = 0.f;
        if (pre) {
            const int n1 = base + (c + 1) * CHUNK + p;
            nx0 = x_c[2 * n1 + 0];
            nx1 = x_c[2 * n1 + 1];
            nyv = y_c[n1];
            ntv = t_c[n1];
            nmk = (mask[n1] != 0) ? 0.0f : 1.0f;
        }

        const float* U  = PLANE(q, 0);
        const float* V  = PLANE(q, 1);
        const float* VY = PLANE(q, 2);
        const float* VT = PLANE(q, 3);

        #pragma unroll 1
        for (int i4 = 0; i4 < 4; i4++) {
            #pragma unroll
            for (int nn = 0; nn < 16; nn++) {
                const int n = i4 * 16 + nn;
                const int vo = n * 64 + gyg * 4;
                const ulonglong2 v2  = *reinterpret_cast<const ulonglong2*>(V  + vo);
                const ulonglong2 vy2 = *reinterpret_cast<const ulonglong2*>(VY + vo);
                const ulonglong2 vt2 = *reinterpret_cast<const ulonglong2*>(VT + vo);
                const float4 u4 = *reinterpret_cast<const float4*>(U + n * 64 + gxg * 4);

                const unsigned long long vv[2] = { v2.x,  v2.y  };
                const unsigned long long vy[2] = { vy2.x, vy2.y };
                const unsigned long long vt[2] = { vt2.x, vt2.y };
                const float uarr[4] = { u4.x, u4.y, u4.z, u4.w };
                #pragma unroll
                for (int i = 0; i < 4; i++) {
                    const unsigned long long us = splat2(uarr[i]);
                    #pragma unroll
                    for (int j = 0; j < 2; j++) {
                        FMA2(aD[i][j], us, vv[j]);
                        FMA2(aY[i][j], us, vy[j]);
                        FMA2(aT[i][j], us, vt[j]);
                    }
                }
            }
            // interleaved Phase A for chunk c+1 (other buffer; MUFU/STS pipes)
            if (pre)
                phaseA_iter(i4, qn, p, gq, nx0, nx1, nyv, ntv, nmk);
        }
        __syncthreads();   // chunk boundary: A(c+1) writes visible, B(c) readers done
    }

    // ---- store partial tile [b][part][ch][gy*64+gx], coalesced STG.128 ----
    float* outp = g_partial + (size_t)(b * NPART + part) * 3 * GG;
    #pragma unroll
    for (int r = 0; r < 4; r++) {                 // gy row within tile
        const int j = r >> 1, hi = r & 1;
        float4 wD, wY, wT;
        float lo0, hi0;
        unpack2(aD[0][j], lo0, hi0); wD.x = hi ? hi0 : lo0;
        unpack2(aD[1][j], lo0, hi0); wD.y = hi ? hi0 : lo0;
        unpack2(aD[2][j], lo0, hi0); wD.z = hi ? hi0 : lo0;
        unpack2(aD[3][j], lo0, hi0); wD.w = hi ? hi0 : lo0;
        unpack2(aY[0][j], lo0, hi0); wY.x = hi ? hi0 : lo0;
        unpack2(aY[1][j], lo0, hi0); wY.y = hi ? hi0 : lo0;
        unpack2(aY[2][j], lo0, hi0); wY.z = hi ? hi0 : lo0;
        unpack2(aY[3][j], lo0, hi0); wY.w = hi ? hi0 : lo0;
        unpack2(aT[0][j], lo0, hi0); wT.x = hi ? hi0 : lo0;
        unpack2(aT[1][j], lo0, hi0); wT.y = hi ? hi0 : lo0;
        unpack2(aT[2][j], lo0, hi0); wT.z = hi ? hi0 : lo0;
        unpack2(aT[3][j], lo0, hi0); wT.w = hi ? hi0 : lo0;
        const int col = (gyg * 4 + r) * 64 + gxg * 4;
        *reinterpret_cast<float4*>(outp +          col) = wD;
        *reinterpret_cast<float4*>(outp + GG     + col) = wY;
        *reinterpret_cast<float4*>(outp + 2 * GG + col) = wT;
    }
}

// Kernel 2: reduce NPART=16 partials, 8-way split-K across threads, normalize.
// grid 1024 blocks (8 b x 128 g-blocks of 32 g) x 256 threads (32 g x 8 splits).
__global__ __launch_bounds__(256)
void rbf_finalize_kernel(float* __restrict__ out)
{
    __shared__ float sD[256], s0[256], s1[256];

    const int b    = blockIdx.x >> 7;
    const int gblk = blockIdx.x & 127;
    const int tid  = threadIdx.x;
    const int gl   = tid & 31;          // g within block
    const int sp   = tid >> 5;          // split 0..7 -> 2 chunks each
    const int g    = gblk * 32 + gl;

    const float* p = g_partial + (size_t)b * NPART * 3 * GG;
    float d = 0.f, a0 = 0.f, a1 = 0.f;
    #pragma unroll
    for (int k = 0; k < NPART / 8; k++) {
        const float* q = p + (size_t)(sp * (NPART / 8) + k) * 3 * GG;
        d  += q[g];
        a0 += q[GG + g];
        a1 += q[2 * GG + g];
    }
    sD[tid] = d; s0[tid] = a0; s1[tid] = a1;
    __syncthreads();

    if (tid < 32) {
        float dd = 0.f, y = 0.f, t = 0.f;
        #pragma unroll
        for (int w = 0; w < 8; w++) {
            dd += sD[tid + 32 * w];
            y  += s0[tid + 32 * w];
            t  += s1[tid + 32 * w];
        }
        float inv = 1.0f / (dd + 1e-5f);
        float* o = out + (size_t)b * 3 * GG;
        o[g]          = dd;
        o[GG + g]     = y * inv;
        o[2 * GG + g] = t * inv;
    }
}

extern "C" void kernel_launch(void* const* d_in, const int* in_sizes, int n_in,
                              void* d_out, int out_size)
{
    const float* x_c  = (const float*)d_in[0];   // (8,4096,2) float32
    const float* y_c  = (const float*)d_in[1];   // (8,4096,1) float32
    const float* t_c  = (const float*)d_in[2];   // (8,4096,1) float32
    const int*   mask = (const int*)d_in[3];     // (8,4096) bool -> int32
    float* out = (float*)d_out;                  // (8,3,64,64) float32

    const int dyn_smem = 2 * 4 * CHUNK * 64 * sizeof(float);   // 128 KB
    static int attr_done = 0;
    if (!attr_done) {
        cudaFuncSetAttribute(rbf_partial_kernel,
                             cudaFuncAttributeMaxDynamicSharedMemorySize, dyn_smem);
        attr_done = 1;
    }

    dim3 grid1(NPART, NB);              // 16 x 8 = 128 blocks, 256 points each
    rbf_partial_kernel<<<grid1, 256, dyn_smem>>>(x_c, y_c, t_c, mask);

    rbf_finalize_kernel<<<NB * 128, 256>>>(out);  // 1024 blocks
}

// round 12
// speedup vs baseline: 1.0099x; 1.0099x over previous
#include <cuda_runtime.h>
#include <cuda_bf16.h>
#include <cstdint>

// Problem constants
#define NB      8
#define NP      4096
#define GG      4096               // 64x64 grid
#define SLICE_N 256                // points per CTA
#define NSLICE  (NP / SLICE_N)     // 16 slices per batch
#define KC      64                 // points per MMA chunk
#define NCHUNK  (SLICE_N / KC)     // 4

// SMEM (dynamic): two 64KB chunk buffers + scalar staging
//   buffer: Ah[192x64 bf16] Al[+24576] Bh[@49152, 64x64] Bl[@57344]
#define BUF_BYTES 65536
#define OFF_AH    0
#define OFF_AL    24576
#define OFF_BH    49152
#define OFF_BL    57344
#define OFF_SCAL  (2 * BUF_BYTES)          // 5 x 64 floats = 1280 B
#define SMEM_BYTES (OFF_SCAL + 1536)

// 128B-row XOR swizzle: byte ^ bits[9:7] into bits[6:4] (16B units)
#define SWZ(x) ((x) ^ (((x) >> 3) & 0x70))

// Partial accumulators: [b][slice][3][GG] -> 8*16*3*4096 floats = 6.3 MB
__device__ float g_partial[NB * NSLICE * 3 * GG];

__device__ __forceinline__ uint32_t smem_u32(const void* p) {
    uint32_t a;
    asm("{ .reg .u64 t; cvta.to.shared.u64 t, %1; cvt.u32.u64 %0, t; }"
        : "=r"(a) : "l"(p));
    return a;
}
__device__ __forceinline__ void ldsm4(uint32_t* r, uint32_t addr) {
    asm volatile("ldmatrix.sync.aligned.m8n8.x4.shared.b16 {%0,%1,%2,%3}, [%4];"
                 : "=r"(r[0]), "=r"(r[1]), "=r"(r[2]), "=r"(r[3]) : "r"(addr));
}
#define MMA(cc, a, b0, b1)                                                     \
    asm volatile(                                                              \
        "mma.sync.aligned.m16n8k16.row.col.f32.bf16.bf16.f32 "                 \
        "{%0,%1,%2,%3},{%4,%5,%6,%7},{%8,%9},{%0,%1,%2,%3};"                   \
        : "+f"((cc)[0]), "+f"((cc)[1]), "+f"((cc)[2]), "+f"((cc)[3])           \
        : "r"((a)[0]), "r"((a)[1]), "r"((a)[2]), "r"((a)[3]),                  \
          "r"(b0), "r"(b1))

// split fp32 pair -> bf16 hi pair + lo pair (packed b32 each)
__device__ __forceinline__ void split_pair(float a0, float a1,
                                           uint32_t& hi, uint32_t& lo) {
    __nv_bfloat16 h0 = __float2bfloat16_rn(a0);
    __nv_bfloat16 h1 = __float2bfloat16_rn(a1);
    __nv_bfloat16 l0 = __float2bfloat16_rn(a0 - __bfloat162float(h0));
    __nv_bfloat16 l1 = __float2bfloat16_rn(a1 - __bfloat162float(h1));
    __nv_bfloat162 hp = __halves2bfloat162(h0, h1), lp = __halves2bfloat162(l0, l1);
    hi = *(uint32_t*)&hp;  lo = *(uint32_t*)&lp;
}

extern __shared__ char dynsm[];

// Kernel 1: per (batch, 256-point slice) CTA, 8 warps.
// A = [V; V*y; V*t] (192 x K), B = U (64 x K); D = A * B^T accumulated in
// fp32 HMMA fragments with 3-term bf16 split (hh + lh + hl).
__global__ __launch_bounds__(256)
void rbf_mma_kernel(const float* __restrict__ x_c, const float* __restrict__ y_c,
                    const float* __restrict__ t_c, const int* __restrict__ mask)
{
    const int slice = blockIdx.x, b = blockIdx.y;
    const int tid = threadIdx.x, wid = tid >> 5, lane = tid & 31;

    char* buf[2] = { dynsm, dynsm + BUF_BYTES };
    float* scal = (float*)(dynsm + OFF_SCAL);      // x0|x1|y|t|m, 64 each

    // ---- build-phase mapping (warp-uniform role) ----
    const int g = tid & 63;                // row within role
    const int q = wid >> 1;                // 0:U 1:V 2:VY 3:VT
    const float cg = -1.0f + (float)g * (2.0f / 63.0f);
    const uint32_t brow = (q == 0) ? (uint32_t)g : (uint32_t)((q - 1) * 64 + g);
    const uint32_t bregion = (q == 0) ? OFF_BH : OFF_AH;
    const uint32_t bdelta  = (q == 0) ? (OFF_BL - OFF_BH) : (OFF_AL - OFF_AH);

    // ---- mma-phase mapping ----
    const int wm = wid & 1, wn = wid >> 1;            // 2 x 4 warp grid
    const int t8 = lane >> 3, r8 = lane & 7;
    const int rofs = (t8 & 1) * 8 + r8;               // row offset within 16-tile
    const int kofs2 = (t8 >> 1) * 16;                 // k byte offset within k16
    const uint32_t xorA = (uint32_t)(r8 << 4);        // swizzle xor (row&7 = r8)
    const int gid = lane >> 2, tig = lane & 3;

    float c[6][2][4];
    #pragma unroll
    for (int i = 0; i < 6; i++)
        #pragma unroll
        for (int j = 0; j < 2; j++)
            #pragma unroll
            for (int k = 0; k < 4; k++) c[i][j][k] = 0.f;

    const int nbase = b * NP + slice * SLICE_N;

    // ---- stage + build chunk 0 ----
    if (tid < KC) {
        int n = nbase + tid;
        float2 xv = ((const float2*)x_c)[n];
        scal[tid] = xv.x;  scal[64 + tid] = xv.y;
        scal[128 + tid] = y_c[n];  scal[192 + tid] = t_c[n];
        scal[256 + tid] = (mask[n] != 0) ? 0.0f : 1.0f;
    }
    __syncthreads();

    #pragma unroll 1
    for (int ch = 0; ch < NCHUNK + 1; ch++) {
        // -------- build chunk ch into buf[ch&1] --------
        if (ch < NCHUNK) {
            char* reg0 = buf[ch & 1] + bregion;
            const uint32_t rb = brow * 128;
            #pragma unroll 4
            for (int k2 = 0; k2 < 32; k2++) {
                const int k = 2 * k2;
                float v0, v1;
                if (q == 0) {
                    float d0 = scal[k] - cg, d1 = scal[k + 1] - cg;
                    v0 = scal[256 + k]     * __expf(-50.f * d0 * d0);
                    v1 = scal[256 + k + 1] * __expf(-50.f * d1 * d1);
                } else {
                    float d0 = scal[64 + k] - cg, d1 = scal[64 + k + 1] - cg;
                    v0 = __expf(-50.f * d0 * d0);
                    v1 = __expf(-50.f * d1 * d1);
                    if (q == 2) { v0 *= scal[128 + k]; v1 *= scal[128 + k + 1]; }
                    if (q == 3) { v0 *= scal[192 + k]; v1 *= scal[192 + k + 1]; }
                }
                uint32_t hi, lo;
                split_pair(v0, v1, hi, lo);
                const uint32_t off = SWZ(rb + (uint32_t)k2 * 4);
                *(uint32_t*)(reg0 + off) = hi;
                *(uint32_t*)(reg0 + bdelta + off) = lo;
            }
        }
        __syncthreads();

        // -------- mma on chunk ch (just built), stage scalars for ch+1 --------
        if (ch < NCHUNK) {
            const uint32_t sb = smem_u32(buf[ch & 1]);
            // per-lane bases
            const uint32_t baseAh = sb + OFF_AH + (uint32_t)(wm * 96 + rofs) * 128;
            const uint32_t baseAl = baseAh + (OFF_AL - OFF_AH);
            const uint32_t rowB   = (uint32_t)(wn * 16 + rofs);
            const uint32_t baseBh = sb + OFF_BH + rowB * 128;
            const uint32_t baseBl = baseBh + (OFF_BL - OFF_BH);
            const uint32_t xorB   = (uint32_t)((rowB & 7) << 4);

            #pragma unroll
            for (int ks = 0; ks < 4; ks++) {
                const uint32_t kb = (uint32_t)(ks * 32 + kofs2);
                uint32_t bh[4], bl[4];
                ldsm4(bh, baseBh + (kb ^ xorB));
                ldsm4(bl, baseBl + (kb ^ xorB));
                #pragma unroll
                for (int mt = 0; mt < 6; mt++) {
                    uint32_t ah[4], al[4];
                    const uint32_t ao = (uint32_t)(mt * 2048) + (kb ^ xorA);
                    ldsm4(ah, baseAh + ao);
                    ldsm4(al, baseAl + ao);
                    MMA(c[mt][0], ah, bh[0], bh[2]);
                    MMA(c[mt][0], al, bh[0], bh[2]);
                    MMA(c[mt][0], ah, bl[0], bl[2]);
                    MMA(c[mt][1], ah, bh[1], bh[3]);
                    MMA(c[mt][1], al, bh[1], bh[3]);
                    MMA(c[mt][1], ah, bl[1], bl[3]);
                }
            }
            // stage next chunk's scalars (not read until after next sync)
            if (ch + 1 < NCHUNK && tid < KC) {
                int n = nbase + (ch + 1) * KC + tid;
                float2 xv = ((const float2*)x_c)[n];
                scal[tid] = xv.x;  scal[64 + tid] = xv.y;
                scal[128 + tid] = y_c[n];  scal[192 + tid] = t_c[n];
                scal[256 + tid] = (mask[n] != 0) ? 0.0f : 1.0f;
            }
        }
        __syncthreads();
    }

    // ---- epilogue: store fragments to g_partial [b][slice][comp][gy*64+gx] ----
    float* pt = g_partial + (size_t)((b * NSLICE + slice) * 3) * GG;
    #pragma unroll
    for (int mt = 0; mt < 6; mt++)
        #pragma unroll
        for (int nt = 0; nt < 2; nt++)
            #pragma unroll
            for (int h = 0; h < 2; h++) {
                const int row = wm * 96 + mt * 16 + gid + h * 8;  // 0..191
                const int col = wn * 16 + nt * 8 + tig * 2;
                const int comp = row >> 6, gy = row & 63;
                float2 val = make_float2(c[mt][nt][h * 2], c[mt][nt][h * 2 + 1]);
                *(float2*)(pt + (size_t)comp * GG + gy * 64 + col) = val;
            }
}

// Kernel 2: reduce NSLICE partials (deep MLP), normalize, write (B,3,64,64).
__global__ __launch_bounds__(256)
void rbf_finalize_kernel(float* __restrict__ out)
{
    const int idx = blockIdx.x * 256 + threadIdx.x;  // over NB*GG = 32768
    const int b = idx >> 12;
    const int g = idx & 4095;

    const float* p = g_partial + (size_t)b * NSLICE * 3 * GG;
    float d = 0.f, s0 = 0.f, s1 = 0.f;
    #pragma unroll
    for (int s = 0; s < NSLICE; s++) {
        const float* q = p + (size_t)s * 3 * GG;
        d  += q[g];
        s0 += q[GG + g];
        s1 += q[2 * GG + g];
    }
    const float inv = 1.0f / (d + 1e-5f);
    float* o = out + (size_t)b * 3 * GG;
    o[g]          = d;
    o[GG + g]     = s0 * inv;
    o[2 * GG + g] = s1 * inv;
}

extern "C" void kernel_launch(void* const* d_in, const int* in_sizes, int n_in,
                              void* d_out, int out_size)
{
    const float* x_c  = (const float*)d_in[0];   // (8,4096,2) float32
    const float* y_c  = (const float*)d_in[1];   // (8,4096,1) float32
    const float* t_c  = (const float*)d_in[2];   // (8,4096,1) float32
    const int*   mask = (const int*)d_in[3];     // (8,4096) bool -> int32
    float* out = (float*)d_out;                  // (8,3,64,64) float32

    static int attr_done = 0;
    if (!attr_done) {
        cudaFuncSetAttribute(rbf_mma_kernel,
                             cudaFuncAttributeMaxDynamicSharedMemorySize, SMEM_BYTES);
        attr_done = 1;
    }

    dim3 grid1(NSLICE, NB);             // 16 x 8 = 128 CTAs
    rbf_mma_kernel<<<grid1, 256, SMEM_BYTES>>>(x_c, y_c, t_c, mask);

    rbf_finalize_kernel<<<(NB * GG) / 256, 256>>>(out);   // 128 blocks
}

// round 16
// speedup vs baseline: 1.1152x; 1.1042x over previous
#include <cuda_runtime.h>
#include <cuda_bf16.h>
#include <cstdint>

// Problem constants
#define NB      8
#define NP      4096
#define GG      4096               // 64x64 grid
#define SLICE_N 256                // points per CTA
#define NSLICE  (NP / SLICE_N)     // 16 slices per batch
#define KC      64                 // points per MMA chunk
#define NCHUNK  (SLICE_N / KC)     // 4

// SMEM (dynamic): two 64KB chunk buffers + two scalar staging buffers
//   buffer: Ah[192x64 bf16] Al[+24576] Bh[@49152, 64x64] Bl[@57344]
#define BUF_BYTES 65536
#define OFF_AH    0
#define OFF_AL    24576
#define OFF_BH    49152
#define OFF_BL    57344
#define OFF_SCAL  (2 * BUF_BYTES)          // 2 x (5 x 64 floats) = 2 x 1280 B
#define SCAL_STRIDE 1408                   // padded
#define SMEM_BYTES (OFF_SCAL + 2 * SCAL_STRIDE + 128)

// 128B-row XOR swizzle: byte ^ bits[9:7] into bits[6:4]
#define SWZ(x) ((x) ^ (((x) >> 3) & 0x70))

// Partial accumulators: [b][slice][3][GG] -> 8*16*3*4096 floats = 6.3 MB
__device__ float g_partial[NB * NSLICE * 3 * GG];

__device__ __forceinline__ uint32_t smem_u32(const void* p) {
    uint32_t a;
    asm("{ .reg .u64 t; cvta.to.shared.u64 t, %1; cvt.u32.u64 %0, t; }"
        : "=r"(a) : "l"(p));
    return a;
}
__device__ __forceinline__ void ldsm4(uint32_t* r, uint32_t addr) {
    asm volatile("ldmatrix.sync.aligned.m8n8.x4.shared.b16 {%0,%1,%2,%3}, [%4];"
                 : "=r"(r[0]), "=r"(r[1]), "=r"(r[2]), "=r"(r[3]) : "r"(addr));
}
#define MMA(cc, a, b0, b1)                                                     \
    asm volatile(                                                              \
        "mma.sync.aligned.m16n8k16.row.col.f32.bf16.bf16.f32 "                 \
        "{%0,%1,%2,%3},{%4,%5,%6,%7},{%8,%9},{%0,%1,%2,%3};"                   \
        : "+f"((cc)[0]), "+f"((cc)[1]), "+f"((cc)[2]), "+f"((cc)[3])           \
        : "r"((a)[0]), "r"((a)[1]), "r"((a)[2]), "r"((a)[3]),                  \
          "r"(b0), "r"(b1))

// fast bf16 split of a float pair: hi = bf16x2(a0,a1), lo = bf16x2(residuals)
// (cvt.rn.bf16x2.f32 first source -> HIGH half, so pass a1 first; a0 -> low,
//  matching __halves2bfloat162(h0, h1) used by the verified R12 layout)
__device__ __forceinline__ void fsplit(float a0, float a1,
                                       uint32_t& hi, uint32_t& lo) {
    asm("cvt.rn.bf16x2.f32 %0, %1, %2;" : "=r"(hi) : "f"(a1), "f"(a0));
    float f0 = __uint_as_float(hi << 16);
    float f1 = __uint_as_float(hi & 0xFFFF0000u);
    asm("cvt.rn.bf16x2.f32 %0, %1, %2;" : "=r"(lo) : "f"(a1 - f1), "f"(a0 - f0));
}

extern __shared__ char dynsm[];

// Build 4 consecutive k-values of this thread's tile row into buffer `dst`.
// k0 multiple of 4. Stores hi/lo as one STS.64 each.
__device__ __forceinline__ void build4(char* dst_hi, char* dst_lo, uint32_t rb,
                                       const float* sc, int k0, int q, float cg)
{
    float v[4];
    if (q == 0) {
        #pragma unroll
        for (int e = 0; e < 4; e++) {
            float d = sc[k0 + e] - cg;
            v[e] = sc[256 + k0 + e] * __expf(-50.f * d * d);
        }
    } else {
        #pragma unroll
        for (int e = 0; e < 4; e++) {
            float d = sc[64 + k0 + e] - cg;
            v[e] = __expf(-50.f * d * d);
        }
        if (q == 2) {
            #pragma unroll
            for (int e = 0; e < 4; e++) v[e] *= sc[128 + k0 + e];
        } else if (q == 3) {
            #pragma unroll
            for (int e = 0; e < 4; e++) v[e] *= sc[192 + k0 + e];
        }
    }
    uint32_t h0, l0, h1, l1;
    fsplit(v[0], v[1], h0, l0);
    fsplit(v[2], v[3], h1, l1);
    const uint32_t off = SWZ(rb + (uint32_t)(k0 * 2));   // 8B-aligned, same 16B unit
    *(uint2*)(dst_hi + off) = make_uint2(h0, h1);
    *(uint2*)(dst_lo + off) = make_uint2(l0, l1);
}

// Kernel 1: per (batch, 256-point slice) CTA, 8 warps.
// A = [V; V*y; V*t] (192 x K), B = U (64 x K); D = A * B^T in fp32 HMMA
// fragments, 3-term bf16 split (hh + lh + hl). Build of chunk ch+1 is
// software-pipelined inside the MMA loop of chunk ch.
__global__ __launch_bounds__(256)
void rbf_mma_kernel(const float* __restrict__ x_c, const float* __restrict__ y_c,
                    const float* __restrict__ t_c, const int* __restrict__ mask)
{
    const int slice = blockIdx.x, b = blockIdx.y;
    const int tid = threadIdx.x, wid = tid >> 5, lane = tid & 31;

    char* buf[2] = { dynsm, dynsm + BUF_BYTES };
    float* scb[2] = { (float*)(dynsm + OFF_SCAL),
                      (float*)(dynsm + OFF_SCAL + SCAL_STRIDE) };

    // ---- build-phase mapping (warp-uniform role) ----
    const int g = tid & 63;                // row within role
    const int q = wid >> 1;                // 0:U 1:V 2:VY 3:VT
    const float cg = -1.0f + (float)g * (2.0f / 63.0f);
    const uint32_t brow = (q == 0) ? (uint32_t)g : (uint32_t)((q - 1) * 64 + g);
    const uint32_t rb = brow * 128;
    const uint32_t bregion = (q == 0) ? OFF_BH : OFF_AH;
    const uint32_t bdelta  = (q == 0) ? (OFF_BL - OFF_BH) : (OFF_AL - OFF_AH);

    // ---- mma-phase mapping ----
    const int wm = wid & 1, wn = wid >> 1;            // 2 x 4 warp grid
    const int t8 = lane >> 3, r8 = lane & 7;
    const int rofs = (t8 & 1) * 8 + r8;               // row offset within 16-tile
    const int kofs2 = (t8 >> 1) * 16;                 // k byte offset within k16
    const uint32_t xorA = (uint32_t)(r8 << 4);
    const int gid = lane >> 2, tig = lane & 3;

    float c[6][2][4];
    #pragma unroll
    for (int i = 0; i < 6; i++)
        #pragma unroll
        for (int j = 0; j < 2; j++)
            #pragma unroll
            for (int k = 0; k < 4; k++) c[i][j][k] = 0.f;

    const int nbase = b * NP + slice * SLICE_N;

    // ---- prologue: stage scal(0); build(0); stage scal(1) ----
    if (tid < KC) {
        int n = nbase + tid;
        float2 xv = ((const float2*)x_c)[n];
        float* s = scb[0];
        s[tid] = xv.x;  s[64 + tid] = xv.y;
        s[128 + tid] = y_c[n];  s[192 + tid] = t_c[n];
        s[256 + tid] = (mask[n] != 0) ? 0.0f : 1.0f;
    }
    __syncthreads();
    {
        char* dh = buf[0] + bregion;
        char* dl = dh + bdelta;
        #pragma unroll 4
        for (int k4 = 0; k4 < 16; k4++)
            build4(dh, dl, rb, scb[0], k4 * 4, q, cg);
        if (tid < KC) {
            int n = nbase + KC + tid;
            float2 xv = ((const float2*)x_c)[n];
            float* s = scb[1];
            s[tid] = xv.x;  s[64 + tid] = xv.y;
            s[128 + tid] = y_c[n];  s[192 + tid] = t_c[n];
            s[256 + tid] = (mask[n] != 0) ? 0.0f : 1.0f;
        }
    }
    __syncthreads();

    // ---- main loop: mma(ch) interleaved with build(ch+1), stage scal(ch+2) ----
    #pragma unroll 1
    for (int ch = 0; ch < NCHUNK; ch++) {
        const uint32_t sb = smem_u32(buf[ch & 1]);
        const uint32_t baseAh = sb + OFF_AH + (uint32_t)(wm * 96 + rofs) * 128;
        const uint32_t baseAl = baseAh + (OFF_AL - OFF_AH);
        const uint32_t rowB   = (uint32_t)(wn * 16 + rofs);
        const uint32_t baseBh = sb + OFF_BH + rowB * 128;
        const uint32_t baseBl = baseBh + (OFF_BL - OFF_BH);
        const uint32_t xorB   = (uint32_t)((rowB & 7) << 4);

        const bool do_build = (ch + 1 < NCHUNK);
        char* dh = buf[(ch + 1) & 1] + bregion;
        char* dl = dh + bdelta;
        const float* nsc = scb[(ch + 1) & 1];

        // stage scal for ch+2 into scb[ch&1] (read next iteration; sync-separated)
        if (ch + 2 < NCHUNK && tid < KC) {
            int n = nbase + (ch + 2) * KC + tid;
            float2 xv = ((const float2*)x_c)[n];
            float* s = scb[ch & 1];
            s[tid] = xv.x;  s[64 + tid] = xv.y;
            s[128 + tid] = y_c[n];  s[192 + tid] = t_c[n];
            s[256 + tid] = (mask[n] != 0) ? 0.0f : 1.0f;
        }

        #pragma unroll
        for (int ks = 0; ks < 4; ks++) {
            const uint32_t kb = (uint32_t)(ks * 32 + kofs2);
            uint32_t bh[4], bl[4];
            ldsm4(bh, baseBh + (kb ^ xorB));
            ldsm4(bl, baseBl + (kb ^ xorB));
            #pragma unroll
            for (int mt = 0; mt < 6; mt++) {
                uint32_t ah[4], al[4];
                const uint32_t ao = (uint32_t)(mt * 2048) + (kb ^ xorA);
                ldsm4(ah, baseAh + ao);
                ldsm4(al, baseAl + ao);
                MMA(c[mt][0], ah, bh[0], bh[2]);
                MMA(c[mt][0], al, bh[0], bh[2]);
                MMA(c[mt][0], ah, bl[0], bl[2]);
                MMA(c[mt][1], ah, bh[1], bh[3]);
                MMA(c[mt][1], al, bh[1], bh[3]);
                MMA(c[mt][1], ah, bl[1], bl[3]);
                // interleaved build of next chunk (2 build4 per mt-pair)
                if (do_build && (mt & 1))
                    build4(dh, dl, rb, nsc, (ks * 4 + (mt >> 1)) * 4 + ks * 0, q, cg);
            }
            // 4th burst of this ks (mt gave 3 bursts: mt=1,3,5 -> k4 = ks*4+0,1,2)
            if (do_build)
                build4(dh, dl, rb, nsc, (ks * 4 + 3) * 4, q, cg);
        }
        __syncthreads();
    }

    // ---- epilogue: store fragments to g_partial [b][slice][comp][gy*64+gx] ----
    float* pt = g_partial + (size_t)((b * NSLICE + slice) * 3) * GG;
    #pragma unroll
    for (int mt = 0; mt < 6; mt++)
        #pragma unroll
        for (int nt = 0; nt < 2; nt++)
            #pragma unroll
            for (int h = 0; h < 2; h++) {
                const int row = wm * 96 + mt * 16 + gid + h * 8;  // 0..191
                const int col = wn * 16 + nt * 8 + tig * 2;
                const int comp = row >> 6, gy = row & 63;
                float2 val = make_float2(c[mt][nt][h * 2], c[mt][nt][h * 2 + 1]);
                *(float2*)(pt + (size_t)comp * GG + gy * 64 + col) = val;
            }
}

// Kernel 2: reduce NSLICE partials (deep MLP), normalize, write (B,3,64,64).
__global__ __launch_bounds__(128)
void rbf_finalize_kernel(float* __restrict__ out)
{
    const int idx = blockIdx.x * 128 + threadIdx.x;  // over NB*GG = 32768
    const int b = idx >> 12;
    const int g = idx & 4095;

    const float* p = g_partial + (size_t)b * NSLICE * 3 * GG;
    float d = 0.f, s0 = 0.f, s1 = 0.f;
    #pragma unroll
    for (int s = 0; s < NSLICE; s++) {
        const float* q = p + (size_t)s * 3 * GG;
        d  += q[g];
        s0 += q[GG + g];
        s1 += q[2 * GG + g];
    }
    const float inv = 1.0f / (d + 1e-5f);
    float* o = out + (size_t)b * 3 * GG;
    o[g]          = d;
    o[GG + g]     = s0 * inv;
    o[2 * GG + g] = s1 * inv;
}

extern "C" void kernel_launch(void* const* d_in, const int* in_sizes, int n_in,
                              void* d_out, int out_size)
{
    const float* x_c  = (const float*)d_in[0];   // (8,4096,2) float32
    const float* y_c  = (const float*)d_in[1];   // (8,4096,1) float32
    const float* t_c  = (const float*)d_in[2];   // (8,4096,1) float32
    const int*   mask = (const int*)d_in[3];     // (8,4096) bool -> int32
    float* out = (float*)d_out;                  // (8,3,64,64) float32

    static int attr_done = 0;
    if (!attr_done) {
        cudaFuncSetAttribute(rbf_mma_kernel,
                             cudaFuncAttributeMaxDynamicSharedMemorySize, SMEM_BYTES);
        attr_done = 1;
    }

    dim3 grid1(NSLICE, NB);             // 16 x 8 = 128 CTAs
    rbf_mma_kernel<<<grid1, 256, SMEM_BYTES>>>(x_c, y_c, t_c, mask);

    rbf_finalize_kernel<<<(NB * GG) / 128, 128>>>(out);   // 256 blocks
}